// round 4
// baseline (speedup 1.0000x reference)
#include <cuda_runtime.h>
#include <math.h>

#define NB 8
#define NC 256
#define NHW 9216
#define NHEAD 8
#define NCP 32

// ---------------- scratch (device globals; no allocation anywhere) ----------
__device__ float  g_v[NB*NC*NHW];      // 75.5 MB
__device__ float  g_S[NB*256*256];     // 2 MB  sum_s x x^T        (per batch)
__device__ float  g_M[NB*256*256];     // 2 MB  sum_s x x_rev^T    (per batch)
__device__ float  g_P[NB*256*256];     // 2 MB  scratch (M*W2^T, then U=W*S)
__device__ float  g_Gf[NB*256*256];    // 2 MB  W1*M*W2^T
__device__ float  g_m[NB*256];
__device__ float  g_nq[NB*256], g_nk[NB*256];
__device__ float  g_w1m[NB*256], g_w2m[NB*256];
__device__ float2 g_Chat[64*1024];
__device__ float2 g_gtab[96*96];
__device__ float2 g_Tt[NB*NC*NHW];     // [ch][a][r]
__device__ float  g_R [NB*NC*NHW];

// ---------------- fp32 SGEMM: Y[b][o][s] = sum_c W[o][c] X[b][c][s] (+bias) --
__global__ void __launch_bounds__(256) k_gemm(
    const float* __restrict__ X, const float* __restrict__ W,
    const float* __restrict__ bias, float* __restrict__ Y)
{
    __shared__ __align__(16) float Ws[8][132];
    __shared__ __align__(16) float Xs[8][132];
    const int t  = threadIdx.x;
    const int s0 = blockIdx.x * 128;
    const int o0 = blockIdx.y * 128;
    const int b  = blockIdx.z;
    const int tx = t & 15, ty = t >> 4;
    const float* Xb = X + (size_t)b * NC * NHW;

    float acc[8][8];
#pragma unroll
    for (int i = 0; i < 8; i++)
#pragma unroll
        for (int j = 0; j < 8; j++) acc[i][j] = 0.f;

    const int wi = t >> 1, wk = (t & 1) * 4;
    const int xr = t >> 5, xc = (t & 31) * 4;

    for (int kc = 0; kc < 256; kc += 8) {
        float4 w4 = *(const float4*)&W[(o0 + wi) * 256 + kc + wk];
        float4 x4 = *(const float4*)&Xb[(size_t)(kc + xr) * NHW + s0 + xc];
        __syncthreads();
        Ws[wk + 0][wi] = w4.x; Ws[wk + 1][wi] = w4.y;
        Ws[wk + 2][wi] = w4.z; Ws[wk + 3][wi] = w4.w;
        *(float4*)&Xs[xr][xc] = x4;
        __syncthreads();
#pragma unroll
        for (int kk = 0; kk < 8; kk++) {
            float a[8], bb[8];
            *(float4*)&a[0]  = *(float4*)&Ws[kk][ty * 4];
            *(float4*)&a[4]  = *(float4*)&Ws[kk][64 + ty * 4];
            *(float4*)&bb[0] = *(float4*)&Xs[kk][tx * 4];
            *(float4*)&bb[4] = *(float4*)&Xs[kk][64 + tx * 4];
#pragma unroll
            for (int i = 0; i < 8; i++)
#pragma unroll
                for (int j = 0; j < 8; j++) acc[i][j] += a[i] * bb[j];
        }
    }
#pragma unroll
    for (int i = 0; i < 8; i++) {
        int o = o0 + ((i < 4) ? ty * 4 + i : 64 + ty * 4 + i - 4);
        float bv = bias ? bias[o] : 0.f;
        float* yp = Y + (size_t)(b * NC + o) * NHW + s0;
        float4 v0 = make_float4(acc[i][0] + bv, acc[i][1] + bv, acc[i][2] + bv, acc[i][3] + bv);
        float4 v1 = make_float4(acc[i][4] + bv, acc[i][5] + bv, acc[i][6] + bv, acc[i][7] + bv);
        *(float4*)&yp[tx * 4]      = v0;
        *(float4*)&yp[64 + tx * 4] = v1;
    }
}

// ---------------- zero S and M ----------------
__global__ void k_zeroSM()
{
    int i = blockIdx.x * 256 + threadIdx.x;   // grid 2048 -> 524288 = 8*65536
    g_S[i] = 0.f;
    g_M[i] = 0.f;
}

// ---------------- m[b][c] = sum_s x[b][c][s] ----------------
__global__ void __launch_bounds__(256) k_xsum(const float* __restrict__ X)
{
    const int bc = blockIdx.x;
    const float4* x4 = (const float4*)(X + (size_t)bc * NHW);
    float s = 0.f;
    for (int i = threadIdx.x; i < NHW / 4; i += 256) {
        float4 a = x4[i]; s += a.x + a.y + a.z + a.w;
    }
#pragma unroll
    for (int o = 16; o; o >>= 1) s += __shfl_xor_sync(0xffffffff, s, o);
    __shared__ float sb[8];
    int w = threadIdx.x >> 5;
    if ((threadIdx.x & 31) == 0) sb[w] = s;
    __syncthreads();
    if (threadIdx.x == 0) {
        float a = 0.f;
        for (int i = 0; i < 8; i++) a += sb[i];
        g_m[bc] = a;
    }
}

// ---------------- Gram kernel: S and M, symmetric tiles, split-K atomics ----
// grid: x=8 s-chunks, y=10 tile pairs (i<=j of 4x4 64-tiles), z = b*2+mat
__global__ void __launch_bounds__(256) k_gram(const float* __restrict__ X)
{
    __constant__ static const int dummy = 0; (void)dummy;
    const int PI_[10] = {0,0,0,0,1,1,1,2,2,3};
    const int PJ_[10] = {0,1,2,3,1,2,3,2,3,3};
    const int sch = blockIdx.x, pr = blockIdx.y;
    const int b = blockIdx.z >> 1, mat = blockIdx.z & 1;
    const int ci = PI_[pr], dj = PJ_[pr];
    __shared__ float xc[64][68];   // [s][c]
    __shared__ float xd[64][68];   // [s][d]
    const float* Xb = X + (size_t)b * NC * NHW;
    const int t = threadIdx.x;
    const int c0 = (t & 15) * 4, d0 = (t >> 4) * 4;

    float acc[4][4];
#pragma unroll
    for (int i = 0; i < 4; i++)
#pragma unroll
        for (int j = 0; j < 4; j++) acc[i][j] = 0.f;

    for (int ks = 0; ks < 18; ks++) {
        const int s0 = sch * 1152 + ks * 64;
        __syncthreads();
#pragma unroll
        for (int i = 0; i < 4; i++) {
            int idx = i * 256 + t;
            int r = idx >> 4, c4 = (idx & 15) * 4;
            float4 v = *(const float4*)&Xb[(size_t)(ci * 64 + r) * NHW + s0 + c4];
            xc[c4 + 0][r] = v.x; xc[c4 + 1][r] = v.y;
            xc[c4 + 2][r] = v.z; xc[c4 + 3][r] = v.w;
        }
        if (mat == 0) {
#pragma unroll
            for (int i = 0; i < 4; i++) {
                int idx = i * 256 + t;
                int r = idx >> 4, c4 = (idx & 15) * 4;
                float4 v = *(const float4*)&Xb[(size_t)(dj * 64 + r) * NHW + s0 + c4];
                xd[c4 + 0][r] = v.x; xd[c4 + 1][r] = v.y;
                xd[c4 + 2][r] = v.z; xd[c4 + 3][r] = v.w;
            }
        } else {
#pragma unroll
            for (int i = 0; i < 16; i++) {
                int idx = i * 256 + t;
                int r = idx >> 6, c = idx & 63;
                int s = s0 + c;
                int y = s / 96, xx = s - y * 96;
                int ry = y == 0 ? 0 : 96 - y;
                int rx = xx == 0 ? 0 : 96 - xx;
                xd[c][r] = Xb[(size_t)(dj * 64 + r) * NHW + ry * 96 + rx];
            }
        }
        __syncthreads();
#pragma unroll 4
        for (int ss = 0; ss < 64; ss++) {
            float a[4], bb[4];
            *(float4*)a  = *(float4*)&xc[ss][c0];
            *(float4*)bb = *(float4*)&xd[ss][d0];
#pragma unroll
            for (int i = 0; i < 4; i++)
#pragma unroll
                for (int j = 0; j < 4; j++) acc[i][j] += a[i] * bb[j];
        }
    }
    float* Out = (mat ? g_M : g_S) + b * 65536;
#pragma unroll
    for (int i = 0; i < 4; i++)
#pragma unroll
        for (int j = 0; j < 4; j++) {
            int cg = ci * 64 + c0 + i, dg = dj * 64 + d0 + j;
            atomicAdd(&Out[cg * 256 + dg], acc[i][j]);
            if (ci != dj) atomicAdd(&Out[dg * 256 + cg], acc[i][j]);
        }
}

// ---------------- P[b] = M[b] * W2^T  (C[i][j] = sum_k M[i,k] W[j,k]) -------
__global__ void __launch_bounds__(256) k_mmA(const float* __restrict__ Wg)
{
    const int j0 = blockIdx.x * 64, i0 = blockIdx.y * 64, b = blockIdx.z;
    const float* A = g_M + b * 65536;
    float* C = g_P + b * 65536;
    __shared__ float As[16][68];
    __shared__ float Bs[16][68];
    const int t = threadIdx.x;
    const int it = (t >> 4) * 4, jt = (t & 15) * 4;
    float acc[4][4];
#pragma unroll
    for (int i = 0; i < 4; i++)
#pragma unroll
        for (int j = 0; j < 4; j++) acc[i][j] = 0.f;
    for (int kc = 0; kc < 256; kc += 16) {
        __syncthreads();
#pragma unroll
        for (int i = 0; i < 4; i++) {
            int idx = i * 256 + t;
            int r = idx >> 4, kk = idx & 15;
            As[kk][r] = A[(i0 + r) * 256 + kc + kk];
            Bs[kk][r] = Wg[(j0 + r) * 256 + kc + kk];
        }
        __syncthreads();
#pragma unroll
        for (int kk = 0; kk < 16; kk++) {
            float a[4], bb[4];
            *(float4*)a  = *(float4*)&As[kk][it];
            *(float4*)bb = *(float4*)&Bs[kk][jt];
#pragma unroll
            for (int i = 0; i < 4; i++)
#pragma unroll
                for (int j = 0; j < 4; j++) acc[i][j] += a[i] * bb[j];
        }
    }
#pragma unroll
    for (int i = 0; i < 4; i++)
#pragma unroll
        for (int j = 0; j < 4; j++)
            C[(i0 + it + i) * 256 + j0 + jt + j] = acc[i][j];
}

// ---------------- C[b] = Ag * B[b]  (C[i][j] = sum_k A[i,k] B[b][k,j]) ------
__global__ void __launch_bounds__(256) k_mmB(
    const float* __restrict__ Ag, const float* __restrict__ Bb, float* __restrict__ Cb)
{
    const int j0 = blockIdx.x * 64, i0 = blockIdx.y * 64, b = blockIdx.z;
    const float* B = Bb + b * 65536;
    float* C = Cb + b * 65536;
    __shared__ float As[16][68];
    __shared__ float Bs[16][68];
    const int t = threadIdx.x;
    const int it = (t >> 4) * 4, jt = (t & 15) * 4;
    float acc[4][4];
#pragma unroll
    for (int i = 0; i < 4; i++)
#pragma unroll
        for (int j = 0; j < 4; j++) acc[i][j] = 0.f;
    for (int kc = 0; kc < 256; kc += 16) {
        __syncthreads();
#pragma unroll
        for (int i = 0; i < 4; i++) {
            int idx = i * 256 + t;
            int r = idx >> 4, kk = idx & 15;
            As[kk][r] = Ag[(i0 + r) * 256 + kc + kk];
        }
#pragma unroll
        for (int i = 0; i < 4; i++) {
            int idx = i * 256 + t;
            int kk = idx >> 6, j = idx & 63;
            Bs[kk][j] = B[(kc + kk) * 256 + j0 + j];
        }
        __syncthreads();
#pragma unroll
        for (int kk = 0; kk < 16; kk++) {
            float a[4], bb[4];
            *(float4*)a  = *(float4*)&As[kk][it];
            *(float4*)bb = *(float4*)&Bs[kk][jt];
#pragma unroll
            for (int i = 0; i < 4; i++)
#pragma unroll
                for (int j = 0; j < 4; j++) acc[i][j] += a[i] * bb[j];
        }
    }
#pragma unroll
    for (int i = 0; i < 4; i++)
#pragma unroll
        for (int j = 0; j < 4; j++)
            C[(i0 + it + i) * 256 + j0 + jt + j] = acc[i][j];
}

// ---------------- row-dot: norms + W*m ----------------
// n[b][C] = sum_j U[b][C][j] W[C][j] + 2 bias[C] wm + 9216 bias^2 ; wm = sum_j W[C,j] m[b][j]
__global__ void __launch_bounds__(256) k_rowdot(
    const float* __restrict__ U, const float* __restrict__ W,
    const float* __restrict__ bias, float* __restrict__ outN, float* __restrict__ outWM)
{
    const int bC = blockIdx.x;           // b*256 + C
    const int b = bC >> 8, C = bC & 255;
    const int t = threadIdx.x;
    float wv = W[C * 256 + t];
    float un = U[(size_t)b * 65536 + C * 256 + t] * wv;
    float wm = wv * g_m[b * 256 + t];
#pragma unroll
    for (int o = 16; o; o >>= 1) {
        un += __shfl_xor_sync(0xffffffff, un, o);
        wm += __shfl_xor_sync(0xffffffff, wm, o);
    }
    __shared__ float s1[8], s2[8];
    int w = t >> 5;
    if ((t & 31) == 0) { s1[w] = un; s2[w] = wm; }
    __syncthreads();
    if (t == 0) {
        float a = 0.f, c = 0.f;
        for (int i = 0; i < 8; i++) { a += s1[i]; c += s2[i]; }
        float bc = bias[C];
        outWM[bC] = c;
        outN[bC] = a + 2.f * bc * c + 9216.f * bc * bc;
    }
}

// ---------------- attn: assemble logits, softmax, build Chat ----------------
__global__ void __launch_bounds__(256) k_attn2(
    const float* __restrict__ b1, const float* __restrict__ b2,
    const float* __restrict__ temperature)
{
    const int bh = blockIdx.x;
    const int b = bh >> 3, h = bh & 7;
    const int ch0 = h * 32;
    __shared__ float A[32][33];
    __shared__ float rq[32], rk[32], sw1m[32], sw2m[32], sb1[32], sb2[32];
    __shared__ float2 tab[32];
    const int t = threadIdx.x;
    if (t < 32) {
        int C = b * 256 + ch0 + t;
        rq[t] = rsqrtf(g_nq[C]);
        rk[t] = rsqrtf(g_nk[C]);
        sw1m[t] = g_w1m[C];
        sw2m[t] = g_w2m[C];
        sb1[t] = b1[ch0 + t];
        sb2[t] = b2[ch0 + t];
        float ang = 6.283185307179586f * (float)t / 32.0f;
        tab[t] = make_float2(cosf(ang), sinf(ang));
    }
    __syncthreads();
    const float ts = temperature[h];
    const int w = t >> 5, lane = t & 31;
    for (int r = w; r < 32; r += 8) {
        float Gv = g_Gf[(size_t)b * 65536 + (ch0 + r) * 256 + ch0 + lane];
        float L = (Gv + sw1m[r] * sb2[lane] + sb1[r] * sw2m[lane]
                   + 9216.f * sb1[r] * sb2[lane]) * rq[r] * rk[lane] * ts;
        float m = L;
#pragma unroll
        for (int o = 16; o; o >>= 1) m = fmaxf(m, __shfl_xor_sync(0xffffffff, m, o));
        float e = expf(L - m);
        float s = e;
#pragma unroll
        for (int o = 16; o; o >>= 1) s += __shfl_xor_sync(0xffffffff, s, o);
        A[r][lane] = e / s;
    }
    __syncthreads();
    for (int idx = t; idx < 1024; idx += 256) {
        int e = idx >> 5, d = idx & 31;
        float re = 0.f, im = 0.f;
#pragma unroll 8
        for (int c = 0; c < 32; c++) {
            float a = A[c][d];
            float2 tb = tab[(c * e) & 31];
            re += a * tb.x; im += a * tb.y;
        }
        re *= (1.0f / 32.0f); im *= (1.0f / 32.0f);
        if (e == 0) im += (1.0f / 32.0f);
        g_Chat[bh * 1024 + idx] = make_float2(re, im);
    }
}

// ---------------- g table (stable half-angle form) ----------------
__global__ void k_gtab()
{
    int idx = blockIdx.x * 256 + threadIdx.x;
    if (idx >= 96 * 96) return;
    int hr = idx / 96, tt = idx - hr * 96;
    float2 g;
    if (hr == 0) {
        g = make_float2(tt == 0 ? 1.f : 0.f, 0.f);
    } else {
        const float PI = 3.14159265358979323846f;
        float h1 = PI * (float)hr / 96.0f;
        float h2 = PI * (96.0f * (float)tt + (float)hr) / 9216.0f;
        float r = sinf(h1) / (96.0f * sinf(h2));
        float psi = h1 - h2;
        g = make_float2(r * cosf(psi), r * sinf(psi));
    }
    g_gtab[idx] = g;
}

// ---------------- v -> Tt directly (fused transpose) ------------------------
// grid (1024 ch-pairs, 3 r-tiles of 32). Tt[ch][a][r] = sum_w v[ch][r][w] g[r][(a-w)%96]
__global__ void __launch_bounds__(256) k_vtrans2()
{
    const int ch0 = blockIdx.x * 2, r0 = blockIdx.y * 32;
    __shared__ float  vsm[2 * 32 * 96];    // 24 KB  [ch*32+r][w]
    __shared__ float2 gsm[32 * 96];        // 24 KB  [r][t]
    const int t = threadIdx.x;
#pragma unroll
    for (int i = 0; i < 6; i++) {
        int idx = i * 256 + t;             // 1536 float4
        int row = idx / 24, c4 = idx % 24;
        int ch = row >> 5, rr = row & 31;
        float4 v = *(const float4*)&g_v[(size_t)(ch0 + ch) * NHW + (r0 + rr) * 96 + c4 * 4];
        *(float4*)&vsm[(ch * 32 + rr) * 96 + c4 * 4] = v;
    }
#pragma unroll
    for (int i = 0; i < 12; i++) {
        int idx = i * 256 + t;             // 3072 float2
        int rr = idx / 96, c = idx % 96;
        gsm[rr * 96 + c] = g_gtab[(r0 + rr) * 96 + c];
    }
    __syncthreads();
    const int lane = t & 31, a0 = (t >> 5) * 12;
    float ar[2][12], ai[2][12];
#pragma unroll
    for (int c = 0; c < 2; c++)
#pragma unroll
        for (int j = 0; j < 12; j++) { ar[c][j] = 0.f; ai[c][j] = 0.f; }

    const float*  v0p = &vsm[lane * 96];
    const float*  v1p = &vsm[(32 + lane) * 96];
    const float2* gp  = &gsm[lane * 96];
    for (int w0 = 0; w0 < 96; w0++) {
        int we = w0 + lane; if (we >= 96) we -= 96;
        float v0 = v0p[we], v1 = v1p[we];
        int base = a0 - we; if (base < 0) base += 96;
#pragma unroll
        for (int j = 0; j < 12; j++) {
            int ii = base + j; if (ii >= 96) ii -= 96;
            float2 g = gp[ii];
            ar[0][j] += v0 * g.x; ai[0][j] += v0 * g.y;
            ar[1][j] += v1 * g.x; ai[1][j] += v1 * g.y;
        }
    }
#pragma unroll
    for (int c = 0; c < 2; c++)
#pragma unroll
        for (int j = 0; j < 12; j++)
            g_Tt[(size_t)(ch0 + c) * NHW + (a0 + j) * 96 + r0 + lane] =
                make_float2(ar[c][j], ai[c][j]);
}

// ---------------- mix: R[bh*32+e][s] = | sum_d Chat[e][d] * Tt[bh*32+d][s] |
__global__ void __launch_bounds__(256) k_mix()
{
    const int s0 = blockIdx.x * 128;
    const int bh = blockIdx.y;
    __shared__ float2 Ch[1024];
    __shared__ float2 Ts[32][128];
    const int t = threadIdx.x;
    for (int i = t; i < 1024; i += 256) Ch[i] = g_Chat[bh * 1024 + i];
    for (int i = t; i < 4096; i += 256) {
        int d = i >> 7, j = i & 127;
        Ts[d][j] = g_Tt[(size_t)(bh * 32 + d) * NHW + s0 + j];
    }
    __syncthreads();
    const int sl = t & 63, eg = t >> 6;
    float ar0[8], ai0[8], ar1[8], ai1[8];
#pragma unroll
    for (int i = 0; i < 8; i++) { ar0[i] = ai0[i] = ar1[i] = ai1[i] = 0.f; }

    for (int d = 0; d < 32; d++) {
        float2 t0 = Ts[d][sl];
        float2 t1 = Ts[d][sl + 64];
#pragma unroll
        for (int i = 0; i < 8; i++) {
            float2 c = Ch[(eg * 8 + i) * 32 + d];
            ar0[i] += c.x * t0.x - c.y * t0.y;
            ai0[i] += c.x * t0.y + c.y * t0.x;
            ar1[i] += c.x * t1.x - c.y * t1.y;
            ai1[i] += c.x * t1.y + c.y * t1.x;
        }
    }
#pragma unroll
    for (int i = 0; i < 8; i++) {
        int row = bh * 32 + eg * 8 + i;
        g_R[(size_t)row * NHW + s0 + sl]      = sqrtf(ar0[i] * ar0[i] + ai0[i] * ai0[i]);
        g_R[(size_t)row * NHW + s0 + sl + 64] = sqrtf(ar1[i] * ar1[i] + ai1[i] * ai1[i]);
    }
}

// ---------------- launch ----------------
extern "C" void kernel_launch(void* const* d_in, const int* in_sizes, int n_in,
                              void* d_out, int out_size)
{
    const float* x    = (const float*)d_in[0];
    const float* w1   = (const float*)d_in[1];
    const float* b1   = (const float*)d_in[2];
    const float* w2   = (const float*)d_in[3];
    const float* b2   = (const float*)d_in[4];
    const float* w3   = (const float*)d_in[5];
    const float* b3   = (const float*)d_in[6];
    const float* wo   = (const float*)d_in[7];
    const float* temp = (const float*)d_in[8];
    float* out = (float*)d_out;

    float *vp = nullptr, *Rp = nullptr, *Sp = nullptr, *Pp = nullptr, *Gfp = nullptr;
    float *nqp = nullptr, *nkp = nullptr, *w1mp = nullptr, *w2mp = nullptr;
    cudaGetSymbolAddress((void**)&vp,  g_v);
    cudaGetSymbolAddress((void**)&Rp,  g_R);
    cudaGetSymbolAddress((void**)&Sp,  g_S);
    cudaGetSymbolAddress((void**)&Pp,  g_P);
    cudaGetSymbolAddress((void**)&Gfp, g_Gf);
    cudaGetSymbolAddress((void**)&nqp,  g_nq);
    cudaGetSymbolAddress((void**)&nkp,  g_nk);
    cudaGetSymbolAddress((void**)&w1mp, g_w1m);
    cudaGetSymbolAddress((void**)&w2mp, g_w2m);

    dim3 gg(72, 2, 8);
    dim3 gm(4, 4, 8);

    k_gemm   <<<gg, 256>>>(x, w3, b3, vp);          // v
    k_zeroSM <<<2048, 256>>>();
    k_xsum   <<<2048, 256>>>(x);
    k_gram   <<<dim3(8, 10, 16), 256>>>(x);         // S, M
    k_mmA    <<<gm, 256>>>(w2);                     // P = M * W2^T
    k_mmB    <<<gm, 256>>>(w1, Pp, Gfp);            // Gf = W1 * P
    k_mmB    <<<gm, 256>>>(w1, Sp, Pp);             // U1 = W1 * S  (reuse P)
    k_rowdot <<<2048, 256>>>(Pp, w1, b1, nqp, w1mp);
    k_mmB    <<<gm, 256>>>(w2, Sp, Pp);             // U2 = W2 * S
    k_rowdot <<<2048, 256>>>(Pp, w2, b2, nkp, w2mp);
    k_gtab   <<<36, 256>>>();
    k_attn2  <<<64, 256>>>(b1, b2, temp);
    k_vtrans2<<<dim3(1024, 3), 256>>>();
    k_mix    <<<dim3(72, 64), 256>>>();
    k_gemm   <<<gg, 256>>>(Rp, wo, nullptr, out);
}